// round 8
// baseline (speedup 1.0000x reference)
#include <cuda_runtime.h>
#include <cstdint>

#define BATCH 4
#define CIN   64
#define COUT  64
#define WDIM  512
#define RES   32
#define VOL   (RES*RES*RES)

// ---------------------------------------------------------------------------
// device globals
// ---------------------------------------------------------------------------
__device__ float g_styles[BATCH * CIN];
// per (b,cin): 8KB = B-matrix [64 cout x 32 taps] tf32, pre-arranged in
// mma.m16n8k8 B-fragment layout: [(ks*8+nt)*32 + lane]*2 + reg
__device__ float g_B[BATCH * CIN * 2048];

__device__ __forceinline__ float f2tf(float f) {
    uint32_t r;
    asm("cvt.rna.tf32.f32 %0, %1;" : "=r"(r) : "f"(f));
    return __uint_as_float(r);
}

__device__ __forceinline__ void mma_tf32(float* c, float a0, float a1, float a2, float a3,
                                         float b0, float b1) {
    asm volatile(
        "mma.sync.aligned.m16n8k8.row.col.f32.tf32.tf32.f32 "
        "{%0,%1,%2,%3}, {%4,%5,%6,%7}, {%8,%9}, {%0,%1,%2,%3};"
        : "+f"(c[0]), "+f"(c[1]), "+f"(c[2]), "+f"(c[3])
        : "r"(__float_as_uint(a0)), "r"(__float_as_uint(a1)),
          "r"(__float_as_uint(a2)), "r"(__float_as_uint(a3)),
          "r"(__float_as_uint(b0)), "r"(__float_as_uint(b1)));
}

// ---------------------------------------------------------------------------
// Kernel A: styles[b][c] = wl[b] . aw[c]/sqrt(512) + ab[c]
// ---------------------------------------------------------------------------
__global__ void k_styles(const float* __restrict__ wl,
                         const float* __restrict__ aw,
                         const float* __restrict__ ab) {
    const int b = blockIdx.x >> 6, c = blockIdx.x & 63;
    const int tid = threadIdx.x;                 // 128
    float acc = 0.f;
    for (int j = tid; j < WDIM; j += 128)
        acc += wl[b * WDIM + j] * aw[c * WDIM + j];
#pragma unroll
    for (int o = 16; o; o >>= 1) acc += __shfl_xor_sync(0xffffffffu, acc, o);
    __shared__ float s[4];
    if ((tid & 31) == 0) s[tid >> 5] = acc;
    __syncthreads();
    if (tid == 0)
        g_styles[blockIdx.x] = (s[0] + s[1] + s[2] + s[3]) * 0.044194173824159216f + ab[c];
}

// ---------------------------------------------------------------------------
// Kernel B: modulate + demodulate -> tf32 B-fragment layout in global
// ---------------------------------------------------------------------------
__global__ void k_wmod(const float* __restrict__ weight) {
    const int b  = blockIdx.x >> 6;
    const int co = blockIdx.x & 63;
    const int tid = threadIdx.x;                 // 256
    __shared__ float s_sty[CIN];
    __shared__ float s_red[8];
    if (tid < CIN) s_sty[tid] = g_styles[b * CIN + tid];
    __syncthreads();
    const float* wr = weight + co * (CIN * 27);
    float s = 0.f;
    for (int i = tid; i < CIN * 27; i += 256) {
        float v = wr[i] * s_sty[i / 27];
        s += v * v;
    }
#pragma unroll
    for (int o = 16; o; o >>= 1) s += __shfl_xor_sync(0xffffffffu, s, o);
    if ((tid & 31) == 0) s_red[tid >> 5] = s;
    __syncthreads();
    if (tid < 32) {
        float t = (tid < 8) ? s_red[tid] : 0.f;
#pragma unroll
        for (int o = 4; o; o >>= 1) t += __shfl_xor_sync(0xffffffffu, t, o);
        if (tid == 0) s_red[0] = t;
    }
    __syncthreads();
    const float d = rsqrtf(s_red[0] + 1e-8f);
    const int nt = co >> 3;
    for (int i = tid; i < CIN * 32; i += 256) {
        const int cin = i >> 5;
        const int t   = i & 31;
        float w = (t < 27) ? wr[cin * 27 + t] * s_sty[cin] * d : 0.f;
        const int ks   = t >> 3;
        const int kk   = t & 7;
        const int reg  = kk >> 2;
        const int lane = ((co & 7) << 2) | (kk & 3);
        const int idx  = (((ks << 3) + nt) * 32 + lane) * 2 + reg;
        g_B[(size_t)(b * CIN + cin) * 2048 + idx] = f2tf(w);
    }
}

// ---------------------------------------------------------------------------
// Kernel C: implicit-GEMM conv via mma.sync tf32 (m16n8k8)
//   CTA: 256 thr / 8 warps; tile: 2 z-planes x 4 y x 32 x (=256 vox), 64 cout
//   warp w: z-plane (w>>2), y-row (w&3); 2 m16 tiles x 8 n8 tiles
//   Double-buffered smem; ONE barrier per cin; LDG prefetch overlaps MMAs.
// ---------------------------------------------------------------------------
#define HPL  240            // halo plane: 6 y * 40 x floats
#define HTOT 960            // 4 planes
#define HVAL 816            // valid staged elements: 4 * 6 * 34

__global__ void __launch_bounds__(256, 2)
k_conv(const float* __restrict__ x,
       const float* __restrict__ noise,
       const float* __restrict__ bias,
       float* __restrict__ out) {
    __shared__ float s_halo[2][HTOT];     // [buf][plane(4)][hy(6)][hx(40)], x=0 at hx=4
    __shared__ float s_B[2][2048];        // [buf] B-fragment tile, 8KB each

    const int tid = threadIdx.x;
    const int wid = tid >> 5;
    const int lid = tid & 31;
    const int r   = lid >> 2;       // fragment row (x offset)
    const int c   = lid & 3;        // fragment k-low / cout pair selector
    const int zoff = wid >> 2;      // which of the 2 z-planes
    const int ywid = wid & 3;       // y row within strip
    const int tile = blockIdx.x;    // 0..127
    const int zt  = tile >> 3;      // z pair index (x2 planes)
    const int y0  = (tile & 7) << 2;
    const int b   = blockIdx.y;
    const int z   = zt * 2 + zoff;
    const int y   = y0 + ywid;

    // Per-thread halo staging map: 4 elems; i = tid + k*256 < 816
    int hidx[4], gofs[4];
#pragma unroll
    for (int k = 0; k < 4; k++) {
        const int i = tid + k * 256;
        if (i < HVAL) {
            const int pl = i / 204, r2 = i - pl * 204;
            const int hy = r2 / 34,  hx = r2 - hy * 34;       // x = hx - 1
            hidx[k] = pl * HPL + hy * 40 + 3 + hx;
            const int gz = zt * 2 - 1 + pl, gy = y0 - 1 + hy, gx = hx - 1;
            gofs[k] = ((unsigned)gz < RES && (unsigned)gy < RES && (unsigned)gx < RES)
                      ? gz * 1024 + gy * 32 + gx : -1;
        } else { hidx[k] = -1; gofs[k] = -1; }
    }

    // Per-thread tap offsets into halo, -1 = padded (zero) tap
    int offA[4], offB[4];
#pragma unroll
    for (int ks = 0; ks < 4; ks++) {
        const int t0 = ks * 8 + c;
        const int t1 = t0 + 4;
        if (t0 < 27) {
            const int dz = t0 / 9, rm = t0 % 9;
            offA[ks] = (zoff + dz) * HPL + (ywid + rm / 3) * 40 + 3 + (rm % 3);
        } else offA[ks] = -1;
        if (t1 < 27) {
            const int dz = t1 / 9, rm = t1 % 9;
            offB[ks] = (zoff + dz) * HPL + (ywid + rm / 3) * 40 + 3 + (rm % 3);
        } else offB[ks] = -1;
    }

    float acc[2][8][4];
#pragma unroll
    for (int mt = 0; mt < 2; mt++)
#pragma unroll
        for (int nt = 0; nt < 8; nt++)
#pragma unroll
            for (int k = 0; k < 4; k++) acc[mt][nt][k] = 0.f;

    const float* xb = x + (size_t)b * CIN * VOL;
    const float4* gB = (const float4*)(g_B + (size_t)b * CIN * 2048);

    // ---- prologue: stage cin 0 into buffer 0 ----
    {
        const float* xc = xb;
#pragma unroll
        for (int k = 0; k < 4; k++)
            if (hidx[k] >= 0)
                s_halo[0][hidx[k]] = f2tf((gofs[k] >= 0) ? __ldg(xc + gofs[k]) : 0.f);
        float4* dst = (float4*)s_B[0];
        dst[tid]       = __ldg(gB + tid);
        dst[tid + 256] = __ldg(gB + tid + 256);
    }
    __syncthreads();

#pragma unroll 1
    for (int cin = 0; cin < CIN; cin++) {
        const int p = cin & 1;

        // ---- prefetch next cin into registers (overlaps MMAs below) ----
        float hv[4];
        float4 bv4[2];
        if (cin + 1 < CIN) {
            const float* xc = xb + (size_t)(cin + 1) * VOL;
#pragma unroll
            for (int k = 0; k < 4; k++)
                hv[k] = (gofs[k] >= 0) ? __ldg(xc + gofs[k]) : 0.f;
            const float4* bsrc = gB + (size_t)(cin + 1) * 512;
            bv4[0] = __ldg(bsrc + tid);
            bv4[1] = __ldg(bsrc + tid + 256);
        }

        // ---- compute on buffer p ----
        const float*  H  = s_halo[p];
        const float2* Bf = (const float2*)s_B[p];
#pragma unroll
        for (int ks = 0; ks < 4; ks++) {
            float2 bv[8];
#pragma unroll
            for (int nt = 0; nt < 8; nt++)
                bv[nt] = Bf[((ks << 3) + nt) * 32 + lid];
#pragma unroll
            for (int mt = 0; mt < 2; mt++) {
                const int base = (mt << 4) + r;
                const float a0 = (offA[ks] >= 0) ? H[offA[ks] + base]     : 0.f;
                const float a1 = (offA[ks] >= 0) ? H[offA[ks] + base + 8] : 0.f;
                const float a2 = (offB[ks] >= 0) ? H[offB[ks] + base]     : 0.f;
                const float a3 = (offB[ks] >= 0) ? H[offB[ks] + base + 8] : 0.f;
#pragma unroll
                for (int nt = 0; nt < 8; nt++)
                    mma_tf32(acc[mt][nt], a0, a1, a2, a3, bv[nt].x, bv[nt].y);
            }
        }

        // ---- commit prefetch to the other buffer; one barrier ----
        if (cin + 1 < CIN) {
            const int q = p ^ 1;
#pragma unroll
            for (int k = 0; k < 4; k++)
                if (hidx[k] >= 0) s_halo[q][hidx[k]] = f2tf(hv[k]);
            float4* dst = (float4*)s_B[q];
            dst[tid]       = bv4[0];
            dst[tid + 256] = bv4[1];
            __syncthreads();
        }
    }

    // ---- epilogue: + noise + bias, lrelu(0.2) * sqrt(2) ----
    const float gain = 1.4142135623730951f;
    const int vrow = z * 1024 + y * 32;
    float nzv[2][2];
#pragma unroll
    for (int mt = 0; mt < 2; mt++) {
        nzv[mt][0] = noise[b * VOL + vrow + (mt << 4) + r];
        nzv[mt][1] = noise[b * VOL + vrow + (mt << 4) + r + 8];
    }
    float2 bp[8];
#pragma unroll
    for (int nt = 0; nt < 8; nt++)
        bp[nt] = *(const float2*)(bias + nt * 8 + 2 * c);

#pragma unroll
    for (int nt = 0; nt < 8; nt++) {
        const int co0 = nt * 8 + 2 * c;
        float* o0 = out + ((size_t)(b * COUT + co0) * VOL) + vrow;
#pragma unroll
        for (int mt = 0; mt < 2; mt++) {
            const int xo = (mt << 4) + r;
            float v0 = acc[mt][nt][0] + nzv[mt][0] + bp[nt].x;
            float v1 = acc[mt][nt][1] + nzv[mt][0] + bp[nt].y;
            float v2 = acc[mt][nt][2] + nzv[mt][1] + bp[nt].x;
            float v3 = acc[mt][nt][3] + nzv[mt][1] + bp[nt].y;
            o0[xo]           = (v0 > 0.f ? v0 : 0.2f * v0) * gain;
            o0[VOL + xo]     = (v1 > 0.f ? v1 : 0.2f * v1) * gain;
            o0[xo + 8]       = (v2 > 0.f ? v2 : 0.2f * v2) * gain;
            o0[VOL + xo + 8] = (v3 > 0.f ? v3 : 0.2f * v3) * gain;
        }
    }
}

// ---------------------------------------------------------------------------
extern "C" void kernel_launch(void* const* d_in, const int* in_sizes, int n_in,
                              void* d_out, int out_size) {
    const float* x      = (const float*)d_in[0];
    const float* wl     = (const float*)d_in[1];
    const float* weight = (const float*)d_in[2];
    const float* aw     = (const float*)d_in[3];
    const float* ab     = (const float*)d_in[4];
    const float* noise  = (const float*)d_in[5];
    const float* bias   = (const float*)d_in[6];
    float* out = (float*)d_out;

    k_styles<<<BATCH * CIN, 128>>>(wl, aw, ab);
    k_wmod<<<BATCH * COUT, 256>>>(weight);
    k_conv<<<dim3(128, BATCH), 256>>>(x, noise, bias, out);
}

// round 9
// speedup vs baseline: 1.3925x; 1.3925x over previous
#include <cuda_runtime.h>
#include <cuda_fp16.h>
#include <cstdint>

#define BATCH 4
#define CIN   64
#define COUT  64
#define WDIM  512
#define RES   32
#define VOL   (RES*RES*RES)

// ---------------------------------------------------------------------------
// device globals
// ---------------------------------------------------------------------------
__device__ float g_styles[BATCH * CIN];
// per (b,cin): 4KB = B-matrix [64 cout x 32 taps] fp16, pre-arranged in
// mma.m16n8k16 B-fragment layout: uint2 at [(ks*8+nt)*32 + lane]
__device__ uint2 g_Bh[BATCH * CIN * 512];

__device__ __forceinline__ uint32_t packh2(float lo, float hi) {
    uint32_t d;
    asm("cvt.rn.f16x2.f32 %0, %1, %2;" : "=r"(d) : "f"(hi), "f"(lo));
    return d;
}

__device__ __forceinline__ void mma_f16(float* c, uint32_t a0, uint32_t a1,
                                        uint32_t a2, uint32_t a3,
                                        uint32_t b0, uint32_t b1) {
    asm volatile(
        "mma.sync.aligned.m16n8k16.row.col.f32.f16.f16.f32 "
        "{%0,%1,%2,%3}, {%4,%5,%6,%7}, {%8,%9}, {%0,%1,%2,%3};"
        : "+f"(c[0]), "+f"(c[1]), "+f"(c[2]), "+f"(c[3])
        : "r"(a0), "r"(a1), "r"(a2), "r"(a3), "r"(b0), "r"(b1));
}

// ---------------------------------------------------------------------------
// Kernel A: styles[b][c] = wl[b] . aw[c]/sqrt(512) + ab[c]
// ---------------------------------------------------------------------------
__global__ void k_styles(const float* __restrict__ wl,
                         const float* __restrict__ aw,
                         const float* __restrict__ ab) {
    const int b = blockIdx.x >> 6, c = blockIdx.x & 63;
    const int tid = threadIdx.x;                 // 128
    float acc = 0.f;
    for (int j = tid; j < WDIM; j += 128)
        acc += wl[b * WDIM + j] * aw[c * WDIM + j];
#pragma unroll
    for (int o = 16; o; o >>= 1) acc += __shfl_xor_sync(0xffffffffu, acc, o);
    __shared__ float s[4];
    if ((tid & 31) == 0) s[tid >> 5] = acc;
    __syncthreads();
    if (tid == 0)
        g_styles[blockIdx.x] = (s[0] + s[1] + s[2] + s[3]) * 0.044194173824159216f + ab[c];
}

// ---------------------------------------------------------------------------
// Kernel B: modulate + demodulate -> fp16 B-fragment layout in global
// ---------------------------------------------------------------------------
__global__ void k_wmod(const float* __restrict__ weight) {
    const int b  = blockIdx.x >> 6;
    const int co = blockIdx.x & 63;
    const int tid = threadIdx.x;                 // 256
    __shared__ float s_sty[CIN];
    __shared__ float s_red[8];
    if (tid < CIN) s_sty[tid] = g_styles[b * CIN + tid];
    __syncthreads();
    const float* wr = weight + co * (CIN * 27);
    float s = 0.f;
    for (int i = tid; i < CIN * 27; i += 256) {
        float v = wr[i] * s_sty[i / 27];
        s += v * v;
    }
#pragma unroll
    for (int o = 16; o; o >>= 1) s += __shfl_xor_sync(0xffffffffu, s, o);
    if ((tid & 31) == 0) s_red[tid >> 5] = s;
    __syncthreads();
    if (tid < 32) {
        float t = (tid < 8) ? s_red[tid] : 0.f;
#pragma unroll
        for (int o = 4; o; o >>= 1) t += __shfl_xor_sync(0xffffffffu, t, o);
        if (tid == 0) s_red[0] = t;
    }
    __syncthreads();
    const float d = rsqrtf(s_red[0] + 1e-8f);
    const int nt = co >> 3;        // n8 tile
    const int rr = co & 7;         // groupID within n8 (lane>>2)
    // items: (cin, ks, c) -> one uint2 (b0={k=2c,2c+1}, b1={k=2c+8,2c+9})
    for (int i = tid; i < CIN * 8; i += 256) {
        const int cin = i >> 3;
        const int ks  = (i >> 2) & 1;
        const int c   = i & 3;
        const int tb  = ks * 16 + 2 * c;
        float w0 = (tb     < 27) ? wr[cin * 27 + tb]     * s_sty[cin] * d : 0.f;
        float w1 = (tb + 1 < 27) ? wr[cin * 27 + tb + 1] * s_sty[cin] * d : 0.f;
        float w2 = (tb + 8 < 27) ? wr[cin * 27 + tb + 8] * s_sty[cin] * d : 0.f;
        float w3 = (tb + 9 < 27) ? wr[cin * 27 + tb + 9] * s_sty[cin] * d : 0.f;
        uint2 v;
        v.x = packh2(w0, w1);
        v.y = packh2(w2, w3);
        g_Bh[((size_t)(b * CIN + cin) * 16 + ks * 8 + nt) * 32 + rr * 4 + c] = v;
    }
}

// ---------------------------------------------------------------------------
// Kernel C: implicit-GEMM conv via mma.sync fp16 (m16n8k16), fp32 accum
//   CTA: 128 thr / 4 warps; tile: z-plane x 4 y x 32 x (=128 vox) x 64 cout
//   warp w: y-row w, 2 m16 tiles, 8 n8 tiles, 2 ksteps/cin
//   R5 skeleton: register prefetch before barrier, 2 syncs per cin.
// ---------------------------------------------------------------------------
__global__ void __launch_bounds__(128, 2)
k_conv(const float* __restrict__ x,
       const float* __restrict__ noise,
       const float* __restrict__ bias,
       float* __restrict__ out) {
    __shared__ float s_halo[3 * 6 * 36];    // [dz][y(6)][x(-1..32, pad 36)] fp32
    __shared__ uint2 s_B[512];              // B-fragment tile, 4KB

    const int tid = threadIdx.x;
    const int wid = tid >> 5;
    const int lid = tid & 31;
    const int r   = lid >> 2;       // groupID (fragment row / n-col)
    const int c   = lid & 3;        // threadID-in-group (k selector)
    const int z   = blockIdx.x >> 3;
    const int y0  = (blockIdx.x & 7) << 2;
    const int b   = blockIdx.y;
    const int y   = y0 + wid;       // this warp's y row

    // Per-thread halo-staging coordinates (5 elements each, index < 612)
    int hidx[5];     // smem float index, -1 if out of tile
    int gofs[5];     // gmem offset within channel, -1 if padded/zero
#pragma unroll
    for (int k = 0; k < 5; k++) {
        const int i = tid + k * 128;
        if (i < 612) {
            const int hz = i / 204, r2 = i - hz * 204;
            const int hy = r2 / 34,  hx = r2 - hy * 34;
            hidx[k] = hz * 216 + hy * 36 + hx;
            const int gz = z - 1 + hz, gy = y0 - 1 + hy, gx = hx - 1;
            gofs[k] = ((unsigned)gz < RES && (unsigned)gy < RES && (unsigned)gx < RES)
                      ? gz * 1024 + gy * 32 + gx : -1;
        } else { hidx[k] = -1; gofs[k] = -1; }
    }

    // Per-thread tap offsets into halo for taps {2c,2c+1,2c+8,2c+9}+16ks.
    // Padded taps (t>=27) point at offset 0: their B columns are exactly zero.
    int offs[2][4];
#pragma unroll
    for (int ks = 0; ks < 2; ks++) {
        const int tb = ks * 16 + 2 * c;
        const int tt[4] = {tb, tb + 1, tb + 8, tb + 9};
#pragma unroll
        for (int j = 0; j < 4; j++) {
            const int t = tt[j];
            if (t < 27) {
                const int dz = t / 9, rm = t % 9;
                offs[ks][j] = dz * 216 + (wid + rm / 3) * 36 + (rm % 3);
            } else offs[ks][j] = 0;
        }
    }

    float acc[2][8][4];
#pragma unroll
    for (int mt = 0; mt < 2; mt++)
#pragma unroll
        for (int nt = 0; nt < 8; nt++)
#pragma unroll
            for (int k = 0; k < 4; k++) acc[mt][nt][k] = 0.f;

    const float* xb = x + (size_t)b * CIN * VOL;
    const uint4* gB = (const uint4*)(g_Bh + (size_t)b * CIN * 512);

#pragma unroll 1
    for (int cin = 0; cin < CIN; cin++) {
        // ---- prefetch (registers only; overlaps previous iter's MMAs) ----
        const float* xc = xb + (size_t)cin * VOL;
        float hv[5];
#pragma unroll
        for (int k = 0; k < 5; k++)
            hv[k] = (gofs[k] >= 0) ? __ldg(xc + gofs[k]) : 0.f;
        const uint4* bsrc = gB + (size_t)cin * 256;
        uint4 bv0 = __ldg(bsrc + tid);
        uint4 bv1 = __ldg(bsrc + tid + 128);

        __syncthreads();   // previous iteration fully consumed

        // ---- commit to smem ----
#pragma unroll
        for (int k = 0; k < 5; k++)
            if (hidx[k] >= 0) s_halo[hidx[k]] = hv[k];
        {
            uint4* dst = (uint4*)s_B;
            dst[tid]       = bv0;
            dst[tid + 128] = bv1;
        }
        __syncthreads();

        // ---- compute: 2 ksteps x 2 mtiles x 8 ntiles ----
#pragma unroll
        for (int ks = 0; ks < 2; ks++) {
            uint2 bv[8];
#pragma unroll
            for (int nt = 0; nt < 8; nt++)
                bv[nt] = s_B[((ks << 3) + nt) * 32 + lid];
            const int o0 = offs[ks][0], o1 = offs[ks][1];
            const int o2 = offs[ks][2], o3 = offs[ks][3];
#pragma unroll
            for (int mt = 0; mt < 2; mt++) {
                const int base = (mt << 4) + r;
                const float h0 = s_halo[o0 + base],     h1 = s_halo[o1 + base];
                const float h2 = s_halo[o2 + base],     h3 = s_halo[o3 + base];
                const float g0 = s_halo[o0 + base + 8], g1 = s_halo[o1 + base + 8];
                const float g2 = s_halo[o2 + base + 8], g3 = s_halo[o3 + base + 8];
                const uint32_t a0 = packh2(h0, h1);
                const uint32_t a1 = packh2(g0, g1);
                const uint32_t a2 = packh2(h2, h3);
                const uint32_t a3 = packh2(g2, g3);
#pragma unroll
                for (int nt = 0; nt < 8; nt++)
                    mma_f16(acc[mt][nt], a0, a1, a2, a3, bv[nt].x, bv[nt].y);
            }
        }
    }

    // ---- epilogue: + noise + bias, lrelu(0.2) * sqrt(2) ----
    const float gain = 1.4142135623730951f;
    const int vrow = z * 1024 + y * 32;
    float nzv[2][2];
#pragma unroll
    for (int mt = 0; mt < 2; mt++) {
        nzv[mt][0] = noise[b * VOL + vrow + (mt << 4) + r];
        nzv[mt][1] = noise[b * VOL + vrow + (mt << 4) + r + 8];
    }
    float2 bp[8];
#pragma unroll
    for (int nt = 0; nt < 8; nt++)
        bp[nt] = *(const float2*)(bias + nt * 8 + 2 * c);

#pragma unroll
    for (int nt = 0; nt < 8; nt++) {
        const int co0 = nt * 8 + 2 * c;
        float* o0 = out + ((size_t)(b * COUT + co0) * VOL) + vrow;
#pragma unroll
        for (int mt = 0; mt < 2; mt++) {
            const int xo = (mt << 4) + r;
            float v0 = acc[mt][nt][0] + nzv[mt][0] + bp[nt].x;
            float v1 = acc[mt][nt][1] + nzv[mt][0] + bp[nt].y;
            float v2 = acc[mt][nt][2] + nzv[mt][1] + bp[nt].x;
            float v3 = acc[mt][nt][3] + nzv[mt][1] + bp[nt].y;
            o0[xo]           = (v0 > 0.f ? v0 : 0.2f * v0) * gain;
            o0[VOL + xo]     = (v1 > 0.f ? v1 : 0.2f * v1) * gain;
            o0[xo + 8]       = (v2 > 0.f ? v2 : 0.2f * v2) * gain;
            o0[VOL + xo + 8] = (v3 > 0.f ? v3 : 0.2f * v3) * gain;
        }
    }
}

// ---------------------------------------------------------------------------
extern "C" void kernel_launch(void* const* d_in, const int* in_sizes, int n_in,
                              void* d_out, int out_size) {
    const float* x      = (const float*)d_in[0];
    const float* wl     = (const float*)d_in[1];
    const float* weight = (const float*)d_in[2];
    const float* aw     = (const float*)d_in[3];
    const float* ab     = (const float*)d_in[4];
    const float* noise  = (const float*)d_in[5];
    const float* bias   = (const float*)d_in[6];
    float* out = (float*)d_out;

    k_styles<<<BATCH * CIN, 128>>>(wl, aw, ab);
    k_wmod<<<BATCH * COUT, 256>>>(weight);
    k_conv<<<dim3(256, BATCH), 128>>>(x, noise, bias, out);
}